// round 15
// baseline (speedup 1.0000x reference)
#include <cuda_runtime.h>

// ---------------------------------------------------------------------------
// Structure (validated R7-R14): CNOT(0,1) couples only wires 0,1 -> circuit
// factorizes as (W on q0q1) x V2 x V3 with M_i = RY(w1)*RZ(w0),
// W = (C*(M0 kron M1))^2, V_i = M_i^2. Folding head_w/head_b:
//   out_j = Horner9(T; cos x0, sin x0, cos x1, sin x1)
//         + U0 cos x2 + U1 sin x2 + U2 cos x3 + U3 sin x3
// R15: R14 shape (128-thr blocks, S=2, warp0 Phase A, trig before the single
// barrier) with a branch-free hot path (B % 256 == 0) and streaming stores.
// ---------------------------------------------------------------------------
template <bool EXACT>
__global__ void __launch_bounds__(128)
fused_kernel(const float4* __restrict__ x4,
             float2* __restrict__ out2,
             const float* __restrict__ w,
             const float* __restrict__ hw,
             const float* __restrict__ hb,
             int B) {
    __shared__ float2 sM[4][4];    // per-wire 2x2 M_i
    __shared__ float2 sN[16];      // N = C*(M0 kron M1)
    __shared__ float2 sW[16];      // W = N*N
    __shared__ float  sG[2][16];   // G_j = Re(W^H Z_j W)
    __shared__ float  sS[2][3];    // singles (a,b,d) for wires 2,3
    __shared__ float2 sT[9];       // pair table (out0, out1)
    __shared__ float2 sU[4];       // (B2, D2, B3, D3) x (out0, out1)

    const int t = threadIdx.x;               // 0..127
    const int i0 = blockIdx.x * 256 + t;     // coalesced
    const int i1 = i0 + 128;

    // ---- issue x loads immediately (latency overlaps Phase A below)
    float4 xa, xb;
    if (EXACT) {
        xa = x4[i0];
        xb = x4[i1];
    } else {
        const float4 z = make_float4(0.f, 0.f, 0.f, 0.f);
        xa = (i0 < B) ? x4[i0] : z;
        xb = (i1 < B) ? x4[i1] : z;
    }

    // ================= Phase A: warp 0 only, syncwarp-staged =================
    if (t < 32) {
        if (t < 4) {
            float sz, cz, sy, cy;
            __sincosf(0.5f * w[t * 4 + 0], &sz, &cz);   // RZ half-angle
            __sincosf(0.5f * w[t * 4 + 1], &sy, &cy);   // RY half-angle
            // M = RY*RZ, e = cz - i sz:  [[cy*e, -sy*e*],[sy*e, cy*e*]]
            sM[t][0] = make_float2( cy * cz, -cy * sz);
            sM[t][1] = make_float2(-sy * cz, -sy * sz);
            sM[t][2] = make_float2( sy * cz, -sy * sz);
            sM[t][3] = make_float2( cy * cz,  cy * sz);
        }
        __syncwarp();
        if (t < 16) {
            // N = C * (M0 kron M1); CNOT permutes rows 2<->3.
            const int r = t >> 2, c = t & 3;
            const int rr = (r == 2) ? 3 : (r == 3) ? 2 : r;
            const float2 a = sM[0][(rr >> 1) * 2 + (c >> 1)];
            const float2 b = sM[1][(rr & 1) * 2 + (c & 1)];
            sN[t] = make_float2(a.x * b.x - a.y * b.y, a.x * b.y + a.y * b.x);
        } else if (t < 18) {
            // Singles: wire q = t-14 (2 or 3). V = M^2, P = V^H Z V.
            const float2* M = sM[t - 14];
            float2 V[4];
            #pragma unroll
            for (int r = 0; r < 2; ++r)
                #pragma unroll
                for (int c = 0; c < 2; ++c) {
                    const float2 p = M[r * 2 + 0], q = M[0 * 2 + c];
                    const float2 p2 = M[r * 2 + 1], q2 = M[1 * 2 + c];
                    V[r * 2 + c] = make_float2(
                        p.x * q.x - p.y * q.y + p2.x * q2.x - p2.y * q2.y,
                        p.x * q.y + p.y * q.x + p2.x * q2.y + p2.y * q2.x);
                }
            const float p00 = V[0].x * V[0].x + V[0].y * V[0].y
                            - (V[2].x * V[2].x + V[2].y * V[2].y);
            const float p11 = V[1].x * V[1].x + V[1].y * V[1].y
                            - (V[3].x * V[3].x + V[3].y * V[3].y);
            const float rp01 = V[0].x * V[1].x + V[0].y * V[1].y
                             - (V[2].x * V[3].x + V[2].y * V[3].y);
            sS[t - 16][0] = 0.5f * (p00 + p11);   // a (constant)
            sS[t - 16][1] = 0.5f * (p00 - p11);   // b (cos coef)
            sS[t - 16][2] = rp01;                 // d (sin coef)
        }
        __syncwarp();
        if (t < 16) {
            // W = N * N (4x4 complex)
            const int r = t >> 2, c = t & 3;
            float ar = 0.0f, ai = 0.0f;
            #pragma unroll
            for (int k = 0; k < 4; ++k) {
                const float2 u = sN[r * 4 + k];
                const float2 v = sN[k * 4 + c];
                ar += u.x * v.x - u.y * v.y;
                ai += u.x * v.y + u.y * v.x;
            }
            sW[t] = make_float2(ar, ai);
        }
        __syncwarp();
        {
            // G_j[k][m] = sum_r zsign_j(r) * Re(conj(W[r,k]) W[r,m])
            const int j = t >> 4, k = (t >> 2) & 3, m = t & 3;
            float g = 0.0f;
            #pragma unroll
            for (int r = 0; r < 4; ++r) {
                const float zs = (j == 0) ? ((r & 2) ? -1.0f : 1.0f)
                                          : ((r & 1) ? -1.0f : 1.0f);
                g += zs * (sW[r * 4 + k].x * sW[r * 4 + m].x +
                           sW[r * 4 + k].y * sW[r * 4 + m].y);
            }
            sG[j][k * 4 + m] = g;
        }
        __syncwarp();
        if (t < 9) {
            // (c^2,cs,s^2) -> (1,cos,sin) transform per axis.
            const float F[3][3] = {{0.5f, 0.5f, 0.0f},
                                   {0.0f, 0.0f, 0.5f},
                                   {0.5f, -0.5f, 0.0f}};
            const int e0 = t / 3, e1 = t % 3;
            const float hw00 = hw[0], hw01 = hw[1], hw10 = hw[4], hw11 = hw[5];
            float a0 = 0.0f, a1 = 0.0f;
            #pragma unroll
            for (int k = 0; k < 4; ++k)
                #pragma unroll
                for (int m = 0; m < 4; ++m) {
                    const int d0 = (k >> 1) + (m >> 1);
                    const int d1 = (k & 1) + (m & 1);
                    const float ww = F[d0][e0] * F[d1][e1];
                    const float g0 = sG[0][k * 4 + m];
                    const float g1 = sG[1][k * 4 + m];
                    a0 += ww * (hw00 * g0 + hw01 * g1);
                    a1 += ww * (hw10 * g0 + hw11 * g1);
                }
            if (t == 0) {  // fold bias + singles' constant terms
                a0 += hb[0] + hw[2] * sS[0][0] + hw[3] * sS[1][0];
                a1 += hb[1] + hw[6] * sS[0][0] + hw[7] * sS[1][0];
            }
            sT[t] = make_float2(a0, a1);
        } else if (t < 13) {
            const int q = (t - 9) >> 1;       // 0 -> wire2, 1 -> wire3
            const int which = (t - 9) & 1;    // 0 -> b (cos), 1 -> d (sin)
            const float v = sS[q][1 + which];
            sU[t - 9] = make_float2(hw[2 + q] * v, hw[6 + q] * v);
        }
    }

    // ---- per-sample trig BEFORE the barrier (overlaps Phase A + load waits)
    float a_sn0, a_cn0, a_sn1, a_cn1, a_sn2, a_cn2, a_sn3, a_cn3;
    float b_sn0, b_cn0, b_sn1, b_cn1, b_sn2, b_cn2, b_sn3, b_cn3;
    __sincosf(xa.x, &a_sn0, &a_cn0);
    __sincosf(xa.y, &a_sn1, &a_cn1);
    __sincosf(xa.z, &a_sn2, &a_cn2);
    __sincosf(xa.w, &a_sn3, &a_cn3);
    __sincosf(xb.x, &b_sn0, &b_cn0);
    __sincosf(xb.y, &b_sn1, &b_cn1);
    __sincosf(xb.z, &b_sn2, &b_cn2);
    __sincosf(xb.w, &b_sn3, &b_cn3);

    __syncthreads();   // the ONLY block barrier (4 warps)

    // ---- table (warp-uniform LDS broadcasts)
    const float2 T0 = sT[0], T1 = sT[1], T2 = sT[2];
    const float2 T3 = sT[3], T4 = sT[4], T5 = sT[5];
    const float2 T6 = sT[6], T7 = sT[7], T8 = sT[8];
    const float2 U0 = sU[0], U1 = sU[1], U2 = sU[2], U3 = sU[3];

    // ---- sample A
    {
        const float e0x = fmaf(a_sn1, T2.x, fmaf(a_cn1, T1.x, T0.x));
        const float e0y = fmaf(a_sn1, T2.y, fmaf(a_cn1, T1.y, T0.y));
        const float e1x = fmaf(a_sn1, T5.x, fmaf(a_cn1, T4.x, T3.x));
        const float e1y = fmaf(a_sn1, T5.y, fmaf(a_cn1, T4.y, T3.y));
        const float e2x = fmaf(a_sn1, T8.x, fmaf(a_cn1, T7.x, T6.x));
        const float e2y = fmaf(a_sn1, T8.y, fmaf(a_cn1, T7.y, T6.y));
        float rx = fmaf(a_sn0, e2x, fmaf(a_cn0, e1x, e0x));
        float ry = fmaf(a_sn0, e2y, fmaf(a_cn0, e1y, e0y));
        rx = fmaf(a_cn2, U0.x, rx);  ry = fmaf(a_cn2, U0.y, ry);
        rx = fmaf(a_sn2, U1.x, rx);  ry = fmaf(a_sn2, U1.y, ry);
        rx = fmaf(a_cn3, U2.x, rx);  ry = fmaf(a_cn3, U2.y, ry);
        rx = fmaf(a_sn3, U3.x, rx);  ry = fmaf(a_sn3, U3.y, ry);
        if (EXACT || i0 < B) __stwt(&out2[i0], make_float2(rx, ry));
    }
    // ---- sample B
    {
        const float e0x = fmaf(b_sn1, T2.x, fmaf(b_cn1, T1.x, T0.x));
        const float e0y = fmaf(b_sn1, T2.y, fmaf(b_cn1, T1.y, T0.y));
        const float e1x = fmaf(b_sn1, T5.x, fmaf(b_cn1, T4.x, T3.x));
        const float e1y = fmaf(b_sn1, T5.y, fmaf(b_cn1, T4.y, T3.y));
        const float e2x = fmaf(b_sn1, T8.x, fmaf(b_cn1, T7.x, T6.x));
        const float e2y = fmaf(b_sn1, T8.y, fmaf(b_cn1, T7.y, T6.y));
        float rx = fmaf(b_sn0, e2x, fmaf(b_cn0, e1x, e0x));
        float ry = fmaf(b_sn0, e2y, fmaf(b_cn0, e1y, e0y));
        rx = fmaf(b_cn2, U0.x, rx);  ry = fmaf(b_cn2, U0.y, ry);
        rx = fmaf(b_sn2, U1.x, rx);  ry = fmaf(b_sn2, U1.y, ry);
        rx = fmaf(b_cn3, U2.x, rx);  ry = fmaf(b_cn3, U2.y, ry);
        rx = fmaf(b_sn3, U3.x, rx);  ry = fmaf(b_sn3, U3.y, ry);
        if (EXACT || i1 < B) __stwt(&out2[i1], make_float2(rx, ry));
    }
}

extern "C" void kernel_launch(void* const* d_in, const int* in_sizes, int n_in,
                              void* d_out, int out_size) {
    const float* x  = (const float*)d_in[0];   // (B, 4) fp32
    const float* w  = (const float*)d_in[1];   // (2, 4, 4) fp32
    const float* hw = (const float*)d_in[2];   // (2, 4) fp32
    const float* hb = (const float*)d_in[3];   // (2,) fp32

    const int B = in_sizes[0] / 4;
    const int grid = (B + 255) / 256;          // 256 samples per 128-thr block

    if ((B & 255) == 0) {
        fused_kernel<true><<<grid, 128>>>((const float4*)x, (float2*)d_out,
                                          w, hw, hb, B);
    } else {
        fused_kernel<false><<<grid, 128>>>((const float4*)x, (float2*)d_out,
                                           w, hw, hb, B);
    }
}

// round 16
// speedup vs baseline: 1.0295x; 1.0295x over previous
#include <cuda_runtime.h>

// ---------------------------------------------------------------------------
// FINAL (R16). Math (validated R7-R15): CNOT(0,1) couples only wires 0,1 ->
// the shared-weight circuit factorizes as (W on q0q1) x V2 x V3 with
// M_i = RY(w[i,1])*RZ(w[i,0]), W = (C*(M0 kron M1))^2, V_i = M_i^2.
// Folding head_w/head_b gives 13 coefficient pairs; per sample:
//   out_j = Horner9(T; cos x0, sin x0, cos x1, sin x1)
//         + U0 cos x2 + U1 sin x2 + U2 cos x3 + U3 sin x3
// Shape: 128-thr blocks, 2 samples/thread, Phase A in warp 0 (syncwarp
// stages), per-sample trig before the single block barrier, plain coalesced
// stores (L2-absorbed). Empirically at the environment floor (8.67 us wall;
// 7 structurally independent designs all pin here with every pipe <40%).
// ---------------------------------------------------------------------------
template <bool EXACT>
__global__ void __launch_bounds__(128)
fused_kernel(const float4* __restrict__ x4,
             float2* __restrict__ out2,
             const float* __restrict__ w,
             const float* __restrict__ hw,
             const float* __restrict__ hb,
             int B) {
    __shared__ float2 sM[4][4];    // per-wire 2x2 M_i
    __shared__ float2 sN[16];      // N = C*(M0 kron M1)
    __shared__ float2 sW[16];      // W = N*N
    __shared__ float  sG[2][16];   // G_j = Re(W^H Z_j W)
    __shared__ float  sS[2][3];    // singles (a,b,d) for wires 2,3
    __shared__ float2 sT[9];       // pair table (out0, out1)
    __shared__ float2 sU[4];       // (B2, D2, B3, D3) x (out0, out1)

    const int t = threadIdx.x;               // 0..127
    const int i0 = blockIdx.x * 256 + t;     // coalesced
    const int i1 = i0 + 128;

    // ---- issue x loads immediately (latency overlaps Phase A below)
    float4 xa, xb;
    if (EXACT) {
        xa = x4[i0];
        xb = x4[i1];
    } else {
        const float4 z = make_float4(0.f, 0.f, 0.f, 0.f);
        xa = (i0 < B) ? x4[i0] : z;
        xb = (i1 < B) ? x4[i1] : z;
    }

    // ================= Phase A: warp 0 only, syncwarp-staged =================
    if (t < 32) {
        if (t < 4) {
            float sz, cz, sy, cy;
            __sincosf(0.5f * w[t * 4 + 0], &sz, &cz);   // RZ half-angle
            __sincosf(0.5f * w[t * 4 + 1], &sy, &cy);   // RY half-angle
            // M = RY*RZ, e = cz - i sz:  [[cy*e, -sy*e*],[sy*e, cy*e*]]
            sM[t][0] = make_float2( cy * cz, -cy * sz);
            sM[t][1] = make_float2(-sy * cz, -sy * sz);
            sM[t][2] = make_float2( sy * cz, -sy * sz);
            sM[t][3] = make_float2( cy * cz,  cy * sz);
        }
        __syncwarp();
        if (t < 16) {
            // N = C * (M0 kron M1); CNOT permutes rows 2<->3.
            const int r = t >> 2, c = t & 3;
            const int rr = (r == 2) ? 3 : (r == 3) ? 2 : r;
            const float2 a = sM[0][(rr >> 1) * 2 + (c >> 1)];
            const float2 b = sM[1][(rr & 1) * 2 + (c & 1)];
            sN[t] = make_float2(a.x * b.x - a.y * b.y, a.x * b.y + a.y * b.x);
        } else if (t < 18) {
            // Singles: wire q = t-14 (2 or 3). V = M^2, P = V^H Z V.
            const float2* M = sM[t - 14];
            float2 V[4];
            #pragma unroll
            for (int r = 0; r < 2; ++r)
                #pragma unroll
                for (int c = 0; c < 2; ++c) {
                    const float2 p = M[r * 2 + 0], q = M[0 * 2 + c];
                    const float2 p2 = M[r * 2 + 1], q2 = M[1 * 2 + c];
                    V[r * 2 + c] = make_float2(
                        p.x * q.x - p.y * q.y + p2.x * q2.x - p2.y * q2.y,
                        p.x * q.y + p.y * q.x + p2.x * q2.y + p2.y * q2.x);
                }
            const float p00 = V[0].x * V[0].x + V[0].y * V[0].y
                            - (V[2].x * V[2].x + V[2].y * V[2].y);
            const float p11 = V[1].x * V[1].x + V[1].y * V[1].y
                            - (V[3].x * V[3].x + V[3].y * V[3].y);
            const float rp01 = V[0].x * V[1].x + V[0].y * V[1].y
                             - (V[2].x * V[3].x + V[2].y * V[3].y);
            sS[t - 16][0] = 0.5f * (p00 + p11);   // a (constant)
            sS[t - 16][1] = 0.5f * (p00 - p11);   // b (cos coef)
            sS[t - 16][2] = rp01;                 // d (sin coef)
        }
        __syncwarp();
        if (t < 16) {
            // W = N * N (4x4 complex)
            const int r = t >> 2, c = t & 3;
            float ar = 0.0f, ai = 0.0f;
            #pragma unroll
            for (int k = 0; k < 4; ++k) {
                const float2 u = sN[r * 4 + k];
                const float2 v = sN[k * 4 + c];
                ar += u.x * v.x - u.y * v.y;
                ai += u.x * v.y + u.y * v.x;
            }
            sW[t] = make_float2(ar, ai);
        }
        __syncwarp();
        {
            // G_j[k][m] = sum_r zsign_j(r) * Re(conj(W[r,k]) W[r,m])
            const int j = t >> 4, k = (t >> 2) & 3, m = t & 3;
            float g = 0.0f;
            #pragma unroll
            for (int r = 0; r < 4; ++r) {
                const float zs = (j == 0) ? ((r & 2) ? -1.0f : 1.0f)
                                          : ((r & 1) ? -1.0f : 1.0f);
                g += zs * (sW[r * 4 + k].x * sW[r * 4 + m].x +
                           sW[r * 4 + k].y * sW[r * 4 + m].y);
            }
            sG[j][k * 4 + m] = g;
        }
        __syncwarp();
        if (t < 9) {
            // (c^2,cs,s^2) -> (1,cos,sin) transform per axis.
            const float F[3][3] = {{0.5f, 0.5f, 0.0f},
                                   {0.0f, 0.0f, 0.5f},
                                   {0.5f, -0.5f, 0.0f}};
            const int e0 = t / 3, e1 = t % 3;
            const float hw00 = hw[0], hw01 = hw[1], hw10 = hw[4], hw11 = hw[5];
            float a0 = 0.0f, a1 = 0.0f;
            #pragma unroll
            for (int k = 0; k < 4; ++k)
                #pragma unroll
                for (int m = 0; m < 4; ++m) {
                    const int d0 = (k >> 1) + (m >> 1);
                    const int d1 = (k & 1) + (m & 1);
                    const float ww = F[d0][e0] * F[d1][e1];
                    const float g0 = sG[0][k * 4 + m];
                    const float g1 = sG[1][k * 4 + m];
                    a0 += ww * (hw00 * g0 + hw01 * g1);
                    a1 += ww * (hw10 * g0 + hw11 * g1);
                }
            if (t == 0) {  // fold bias + singles' constant terms
                a0 += hb[0] + hw[2] * sS[0][0] + hw[3] * sS[1][0];
                a1 += hb[1] + hw[6] * sS[0][0] + hw[7] * sS[1][0];
            }
            sT[t] = make_float2(a0, a1);
        } else if (t < 13) {
            const int q = (t - 9) >> 1;       // 0 -> wire2, 1 -> wire3
            const int which = (t - 9) & 1;    // 0 -> b (cos), 1 -> d (sin)
            const float v = sS[q][1 + which];
            sU[t - 9] = make_float2(hw[2 + q] * v, hw[6 + q] * v);
        }
    }

    // ---- per-sample trig BEFORE the barrier (overlaps Phase A + load waits)
    float a_sn0, a_cn0, a_sn1, a_cn1, a_sn2, a_cn2, a_sn3, a_cn3;
    float b_sn0, b_cn0, b_sn1, b_cn1, b_sn2, b_cn2, b_sn3, b_cn3;
    __sincosf(xa.x, &a_sn0, &a_cn0);
    __sincosf(xa.y, &a_sn1, &a_cn1);
    __sincosf(xa.z, &a_sn2, &a_cn2);
    __sincosf(xa.w, &a_sn3, &a_cn3);
    __sincosf(xb.x, &b_sn0, &b_cn0);
    __sincosf(xb.y, &b_sn1, &b_cn1);
    __sincosf(xb.z, &b_sn2, &b_cn2);
    __sincosf(xb.w, &b_sn3, &b_cn3);

    __syncthreads();   // the ONLY block barrier (4 warps)

    // ---- table (warp-uniform LDS broadcasts)
    const float2 T0 = sT[0], T1 = sT[1], T2 = sT[2];
    const float2 T3 = sT[3], T4 = sT[4], T5 = sT[5];
    const float2 T6 = sT[6], T7 = sT[7], T8 = sT[8];
    const float2 U0 = sU[0], U1 = sU[1], U2 = sU[2], U3 = sU[3];

    // ---- sample A
    {
        const float e0x = fmaf(a_sn1, T2.x, fmaf(a_cn1, T1.x, T0.x));
        const float e0y = fmaf(a_sn1, T2.y, fmaf(a_cn1, T1.y, T0.y));
        const float e1x = fmaf(a_sn1, T5.x, fmaf(a_cn1, T4.x, T3.x));
        const float e1y = fmaf(a_sn1, T5.y, fmaf(a_cn1, T4.y, T3.y));
        const float e2x = fmaf(a_sn1, T8.x, fmaf(a_cn1, T7.x, T6.x));
        const float e2y = fmaf(a_sn1, T8.y, fmaf(a_cn1, T7.y, T6.y));
        float rx = fmaf(a_sn0, e2x, fmaf(a_cn0, e1x, e0x));
        float ry = fmaf(a_sn0, e2y, fmaf(a_cn0, e1y, e0y));
        rx = fmaf(a_cn2, U0.x, rx);  ry = fmaf(a_cn2, U0.y, ry);
        rx = fmaf(a_sn2, U1.x, rx);  ry = fmaf(a_sn2, U1.y, ry);
        rx = fmaf(a_cn3, U2.x, rx);  ry = fmaf(a_cn3, U2.y, ry);
        rx = fmaf(a_sn3, U3.x, rx);  ry = fmaf(a_sn3, U3.y, ry);
        if (EXACT || i0 < B) out2[i0] = make_float2(rx, ry);
    }
    // ---- sample B
    {
        const float e0x = fmaf(b_sn1, T2.x, fmaf(b_cn1, T1.x, T0.x));
        const float e0y = fmaf(b_sn1, T2.y, fmaf(b_cn1, T1.y, T0.y));
        const float e1x = fmaf(b_sn1, T5.x, fmaf(b_cn1, T4.x, T3.x));
        const float e1y = fmaf(b_sn1, T5.y, fmaf(b_cn1, T4.y, T3.y));
        const float e2x = fmaf(b_sn1, T8.x, fmaf(b_cn1, T7.x, T6.x));
        const float e2y = fmaf(b_sn1, T8.y, fmaf(b_cn1, T7.y, T6.y));
        float rx = fmaf(b_sn0, e2x, fmaf(b_cn0, e1x, e0x));
        float ry = fmaf(b_sn0, e2y, fmaf(b_cn0, e1y, e0y));
        rx = fmaf(b_cn2, U0.x, rx);  ry = fmaf(b_cn2, U0.y, ry);
        rx = fmaf(b_sn2, U1.x, rx);  ry = fmaf(b_sn2, U1.y, ry);
        rx = fmaf(b_cn3, U2.x, rx);  ry = fmaf(b_cn3, U2.y, ry);
        rx = fmaf(b_sn3, U3.x, rx);  ry = fmaf(b_sn3, U3.y, ry);
        if (EXACT || i1 < B) out2[i1] = make_float2(rx, ry);
    }
}

extern "C" void kernel_launch(void* const* d_in, const int* in_sizes, int n_in,
                              void* d_out, int out_size) {
    const float* x  = (const float*)d_in[0];   // (B, 4) fp32
    const float* w  = (const float*)d_in[1];   // (2, 4, 4) fp32
    const float* hw = (const float*)d_in[2];   // (2, 4) fp32
    const float* hb = (const float*)d_in[3];   // (2,) fp32

    const int B = in_sizes[0] / 4;
    const int grid = (B + 255) / 256;          // 256 samples per 128-thr block

    if ((B & 255) == 0) {
        fused_kernel<true><<<grid, 128>>>((const float4*)x, (float2*)d_out,
                                          w, hw, hb, B);
    } else {
        fused_kernel<false><<<grid, 128>>>((const float4*)x, (float2*)d_out,
                                           w, hw, hb, B);
    }
}